// round 10
// baseline (speedup 1.0000x reference)
#include <cuda_runtime.h>
#include <cuda_fp16.h>
#include <cuda_bf16.h>

#define NN 50000
#define NE 800000
#define HID 64
#define NB 49   // scan blocks: ceil(50000/1024)

// ---------------- scratch (device globals; no allocation allowed) -------------
__device__ float   g_xs[NN * 4];         // dinv[n] * x[n]  (pre-scaled input)
__device__ __half  g_bufAh[NN * HID];    // hidden GEMM output, pre-scaled fp16
__device__ __half  g_bufBh[NN * HID];    // aggregation output (fp16)
__device__ float   g_z[NN];              // pre-scaled final scalar  dinv[n]*z[n]
__device__ float   g_dinv[NN];
__device__ int     g_cnt[NN];
__device__ int     g_rowptr[NN + 1];
__device__ int     g_fill[NN];
__device__ int     g_col[NE];
__device__ int     g_bsum[NB];

// ---------------- CSR build --------------------------------------------------
__global__ void k_zero_cnt() {
    int i = blockIdx.x * blockDim.x + threadIdx.x;
    if (i < NN) g_cnt[i] = 0;
}

__global__ void k_count(const int* __restrict__ ei) {
    int e = blockIdx.x * blockDim.x + threadIdx.x;
    if (e < NE) atomicAdd(&g_cnt[ei[NE + e]], 1);
}

// merged: dinv + xs pre-scale + per-1024-chunk count sums (grid NB x 1024)
__global__ void k_dinv_blocksum(const float* __restrict__ x) {
    __shared__ int sw[32];
    int tid = threadIdx.x;
    int i = blockIdx.x * 1024 + tid;
    int c = 0;
    if (i < NN) {
        c = g_cnt[i];
        float di = rsqrtf((float)(c + 1));  // +1 self loop
        g_dinv[i] = di;
        float4 v = ((const float4*)x)[i];
        v.x *= di; v.y *= di; v.z *= di; v.w *= di;
        ((float4*)g_xs)[i] = v;
    }
    int v = c;
    #pragma unroll
    for (int o = 16; o; o >>= 1) v += __shfl_xor_sync(0xffffffffu, v, o);
    if ((tid & 31) == 0) sw[tid >> 5] = v;
    __syncthreads();
    if (tid < 32) {
        int s = sw[tid];
        #pragma unroll
        for (int o = 16; o; o >>= 1) s += __shfl_xor_sync(0xffffffffu, s, o);
        if (tid == 0) g_bsum[blockIdx.x] = s;
    }
}

// exclusive scan within chunk; block prefix computed inline from g_bsum
__global__ void k_scanfinal() {
    __shared__ int swarp[32];
    __shared__ int sPref;
    int lane = threadIdx.x & 31, wid = threadIdx.x >> 5;
    int bid = blockIdx.x;
    // warp 0: prefix sum of bsum[0..bid)
    if (wid == 0) {
        int p = 0;
        for (int b = lane; b < bid; b += 32) p += g_bsum[b];
        #pragma unroll
        for (int o = 16; o; o >>= 1) p += __shfl_xor_sync(0xffffffffu, p, o);
        if (lane == 0) {
            sPref = p;
            if (bid == NB - 1) g_rowptr[NN] = p + g_bsum[NB - 1];
        }
    }
    int i = bid * 1024 + threadIdx.x;
    int v = (i < NN) ? g_cnt[i] : 0;
    int incl = v;
    #pragma unroll
    for (int o = 1; o < 32; o <<= 1) {
        int t = __shfl_up_sync(0xffffffffu, incl, o);
        if (lane >= o) incl += t;
    }
    if (lane == 31) swarp[wid] = incl;
    __syncthreads();
    if (wid == 0) {
        int s = swarp[lane];
        int si = s;
        #pragma unroll
        for (int o = 1; o < 32; o <<= 1) {
            int t = __shfl_up_sync(0xffffffffu, si, o);
            if (lane >= o) si += t;
        }
        swarp[lane] = si - s;
    }
    __syncthreads();
    if (i < NN) {
        int excl = incl - v + swarp[wid] + sPref;
        g_rowptr[i] = excl;
        g_fill[i]   = excl;
    }
}

__global__ void k_scatter(const int* __restrict__ ei) {
    int e = blockIdx.x * blockDim.x + threadIdx.x;
    if (e < NE) {
        int s = ei[e];
        int d = ei[NE + e];
        int pos = atomicAdd(&g_fill[d], 1);
        g_col[pos] = s;
    }
}

// ------- layer 0 fused: h0 = relu( [dinv*(sum xs + xs_self)] @ W_in + b ) ------
// warp per node; butterfly reduce leaves full 4-vector in every lane;
// lane then computes features 2l, 2l+1 and stores half2 -> bufBh
__global__ void k_aggx_gemm(const float* __restrict__ W, const float* __restrict__ bias) {
    __shared__ float2 Ws2[4 * 32];   // W_in[k][2l..2l+1]
    __shared__ float2 Bs2[32];
    if (threadIdx.x < 128) {
        int k = threadIdx.x >> 5, l = threadIdx.x & 31;
        Ws2[k * 32 + l] = make_float2(W[k * HID + 2 * l], W[k * HID + 2 * l + 1]);
    }
    if (threadIdx.x < 32)
        Bs2[threadIdx.x] = make_float2(bias[2 * threadIdx.x], bias[2 * threadIdx.x + 1]);
    __syncthreads();

    int warp = (blockIdx.x * blockDim.x + threadIdx.x) >> 5;
    int lane = threadIdx.x & 31;
    if (warp >= NN) return;
    int n = warp;
    const float4* xs4 = (const float4*)g_xs;
    float4 acc = make_float4(0.f, 0.f, 0.f, 0.f);
    int beg = g_rowptr[n], end = g_rowptr[n + 1];
    for (int j = beg + lane; j < end; j += 32) {
        float4 v = __ldg(&xs4[g_col[j]]);
        acc.x += v.x; acc.y += v.y; acc.z += v.z; acc.w += v.w;
    }
    #pragma unroll
    for (int o = 16; o; o >>= 1) {
        acc.x += __shfl_xor_sync(0xffffffffu, acc.x, o);
        acc.y += __shfl_xor_sync(0xffffffffu, acc.y, o);
        acc.z += __shfl_xor_sync(0xffffffffu, acc.z, o);
        acc.w += __shfl_xor_sync(0xffffffffu, acc.w, o);
    }
    float di = g_dinv[n];
    float4 sv = xs4[n];
    float y0 = di * (acc.x + sv.x);
    float y1 = di * (acc.y + sv.y);
    float y2 = di * (acc.z + sv.z);
    float y3 = di * (acc.w + sv.w);
    float2 b2 = Bs2[lane];
    float a0 = b2.x, a1 = b2.y;
    float2 w0 = Ws2[0 * 32 + lane], w1 = Ws2[1 * 32 + lane];
    float2 w2 = Ws2[2 * 32 + lane], w3 = Ws2[3 * 32 + lane];
    a0 = fmaf(y0, w0.x, a0); a1 = fmaf(y0, w0.y, a1);
    a0 = fmaf(y1, w1.x, a0); a1 = fmaf(y1, w1.y, a1);
    a0 = fmaf(y2, w2.x, a0); a1 = fmaf(y2, w2.y, a1);
    a0 = fmaf(y3, w3.x, a0); a1 = fmaf(y3, w3.y, a1);
    a0 = fmaxf(a0, 0.f);
    a1 = fmaxf(a1, 0.f);
    ((__half2*)g_bufBh)[n * 32 + lane] = __floats2half2_rn(a0, a1);
}

// ------ hidden dense: bufBh(fp16) @ W, pre-scaled by dinv[n] -> bufAh fp16 -----
__global__ void k_gemm64(const float* __restrict__ W) {
    __shared__ float Ws[HID * HID];
    __shared__ __align__(16) float Hs[4 * HID];
    for (int i = threadIdx.x; i < HID * HID; i += blockDim.x) Ws[i] = W[i];
    int nodeBase = blockIdx.x * 64;
    int f  = threadIdx.x & 63;
    int nl = threadIdx.x >> 6;
    for (int c = 0; c < 64; c += 4) {
        __syncthreads();
        int n = nodeBase + c + nl;
        Hs[nl * HID + f] = (n < NN) ? __half2float(g_bufBh[n * HID + f]) : 0.f;
        __syncthreads();
        if (n < NN) {
            const float4* H4 = (const float4*)&Hs[nl * HID];
            float acc = 0.f;
            #pragma unroll
            for (int k4 = 0; k4 < 16; k4++) {
                float4 h = H4[k4];
                acc = fmaf(h.x, Ws[(4 * k4 + 0) * HID + f], acc);
                acc = fmaf(h.y, Ws[(4 * k4 + 1) * HID + f], acc);
                acc = fmaf(h.z, Ws[(4 * k4 + 2) * HID + f], acc);
                acc = fmaf(h.w, Ws[(4 * k4 + 3) * HID + f], acc);
            }
            acc *= g_dinv[n];  // pre-scale: hs = dinv[n] * (h @ W)
            float accHi = __shfl_down_sync(0xffffffffu, acc, 1);
            if ((f & 1) == 0)
                ((__half2*)g_bufAh)[n * 32 + (f >> 1)] = __floats2half2_rn(acc, accHi);
        }
    }
}

// ---- hidden aggregation: warp/node, unweighted half2 gathers, fp32 accum -----
// LAST=false: bufBh = half2(relu(di*agg + bias))
// LAST=true : g_z[n] = di * (relu(di*agg + bias) . Wout)   (fp32 path)
template <bool LAST>
__global__ void k_agg64(const float* __restrict__ bias, const float* __restrict__ Wout) {
    int warp = (blockIdx.x * blockDim.x + threadIdx.x) >> 5;
    int lane = threadIdx.x & 31;
    if (warp >= NN) return;
    int n = warp;
    const __half2* A2 = (const __half2*)g_bufAh;
    float ax = 0.f, ay = 0.f;
    int beg = g_rowptr[n], end = g_rowptr[n + 1];
    for (int j = beg; j < end; j++) {
        int s = g_col[j];
        float2 v = __half22float2(__ldg(&A2[s * 32 + lane]));
        ax += v.x;
        ay += v.y;
    }
    float2 sv = __half22float2(A2[n * 32 + lane]);
    ax += sv.x;
    ay += sv.y;
    float di = g_dinv[n];
    float2 b2 = ((const float2*)bias)[lane];
    ax = fmaxf(fmaf(di, ax, b2.x), 0.f);
    ay = fmaxf(fmaf(di, ay, b2.y), 0.f);
    if (!LAST) {
        ((__half2*)g_bufBh)[n * 32 + lane] = __floats2half2_rn(ax, ay);
    } else {
        float2 w2 = ((const float2*)Wout)[lane];
        float s = ax * w2.x + ay * w2.y;
        #pragma unroll
        for (int o = 16; o; o >>= 1) s += __shfl_xor_sync(0xffffffffu, s, o);
        if (lane == 0) g_z[n] = di * s;   // pre-scaled zs
    }
}

// ---- final scalar aggregation: out[n] = dinv[n]*(Sum zs[src] + zs[n]) + b ----
__global__ void k_agg_scalar(float* __restrict__ out, const float* __restrict__ b_out) {
    int n = blockIdx.x * blockDim.x + threadIdx.x;
    if (n < NN) {
        float acc = 0.f;
        int beg = g_rowptr[n], end = g_rowptr[n + 1];
        for (int j = beg; j < end; j++) acc += __ldg(&g_z[g_col[j]]);
        acc += g_z[n];
        out[n] = fmaf(g_dinv[n], acc, b_out[0]);
    }
}

// ---------------- launch ------------------------------------------------------
extern "C" void kernel_launch(void* const* d_in, const int* in_sizes, int n_in,
                              void* d_out, int out_size) {
    const float* x     = (const float*)d_in[0];
    const int*   ei    = (const int*)d_in[1];
    const float* W_in  = (const float*)d_in[2];
    const float* b_in  = (const float*)d_in[3];
    const float* W_h   = (const float*)d_in[4];
    const float* b_h   = (const float*)d_in[5];
    const float* W_out = (const float*)d_in[6];
    const float* b_out = (const float*)d_in[7];
    float*       out   = (float*)d_out;

    const int TB = 256;
    const int gN  = (NN + TB - 1) / TB;
    const int gE  = (NE + TB - 1) / TB;
    const int gW  = (NN * 32 + TB - 1) / TB;
    const int gG  = (NN + 63) / 64;

    // CSR build (+ dinv/xs pre-scale fused)
    k_zero_cnt<<<gN, TB>>>();
    k_count<<<gE, TB>>>(ei);
    k_dinv_blocksum<<<NB, 1024>>>(x);
    k_scanfinal<<<NB, 1024>>>();
    k_scatter<<<gE, TB>>>(ei);

    // layer 0 (agg + gemm fused)
    k_aggx_gemm<<<gW, TB>>>(W_in, b_in);

    // hidden layers 1-2
    for (int l = 0; l < 2; l++) {
        k_gemm64<<<gG, TB>>>(W_h + l * HID * HID);
        k_agg64<false><<<gW, TB>>>(b_h + l * HID, nullptr);
    }
    // hidden layer 3 with fused output GEMM
    k_gemm64<<<gG, TB>>>(W_h + 2 * HID * HID);
    k_agg64<true><<<gW, TB>>>(b_h + 2 * HID, W_out);

    // final scalar aggregation
    k_agg_scalar<<<gN, TB>>>(out, b_out);
}

// round 11
// speedup vs baseline: 1.0578x; 1.0578x over previous
#include <cuda_runtime.h>
#include <cuda_fp16.h>
#include <cuda_bf16.h>

#define NN 50000
#define NE 800000
#define HID 64
#define MAXD 128   // per-node bucket capacity (Poisson(16) tail @128 ~ 0)

// ---------------- scratch (device globals; no allocation allowed) -------------
__device__ float   g_xs[NN * 4];         // dinv[n] * x[n]
__device__ __half  g_bufAh[NN * HID];    // hidden GEMM output, pre-scaled fp16
__device__ __half  g_bufBh[NN * HID];    // aggregation output (fp16)
__device__ float   g_z[NN];              // pre-scaled final scalar
__device__ float   g_dinv[NN];
__device__ int     g_cnt[NN];
__device__ int     g_col[NN * MAXD];     // bucketed CSR (row n at n*MAXD)

// ---------------- CSR build (bucketed: count IS scatter) -----------------------
__global__ void k_zero_cnt() {
    int i = blockIdx.x * blockDim.x + threadIdx.x;
    if (i < NN) g_cnt[i] = 0;
}

__global__ void k_scatter_count(const int* __restrict__ ei) {
    int e = blockIdx.x * blockDim.x + threadIdx.x;
    if (e < NE) {
        int s = ei[e];
        int d = ei[NE + e];
        int pos = atomicAdd(&g_cnt[d], 1);
        if (pos < MAXD) g_col[d * MAXD + pos] = s;
    }
}

// dinv + pre-scaled input xs = dinv[n]*x[n]
__global__ void k_dinv_xs(const float* __restrict__ x) {
    int i = blockIdx.x * blockDim.x + threadIdx.x;
    if (i < NN) {
        float di = rsqrtf((float)(g_cnt[i] + 1));  // +1 self loop
        g_dinv[i] = di;
        float4 v = ((const float4*)x)[i];
        v.x *= di; v.y *= di; v.z *= di; v.w *= di;
        ((float4*)g_xs)[i] = v;
    }
}

// ------- layer 0 fused: h0 = relu( [dinv*(sum xs + xs_self)] @ W_in + b ) ------
__global__ void k_aggx_gemm(const float* __restrict__ W, const float* __restrict__ bias) {
    __shared__ float2 Ws2[4 * 32];
    __shared__ float2 Bs2[32];
    if (threadIdx.x < 128) {
        int k = threadIdx.x >> 5, l = threadIdx.x & 31;
        Ws2[k * 32 + l] = make_float2(W[k * HID + 2 * l], W[k * HID + 2 * l + 1]);
    }
    if (threadIdx.x < 32)
        Bs2[threadIdx.x] = make_float2(bias[2 * threadIdx.x], bias[2 * threadIdx.x + 1]);
    __syncthreads();

    int warp = (blockIdx.x * blockDim.x + threadIdx.x) >> 5;
    int lane = threadIdx.x & 31;
    if (warp >= NN) return;
    int n = warp;
    const float4* xs4 = (const float4*)g_xs;
    float4 acc = make_float4(0.f, 0.f, 0.f, 0.f);
    int base = n * MAXD;
    int len = min(g_cnt[n], MAXD);
    for (int j = lane; j < len; j += 32) {
        float4 v = __ldg(&xs4[g_col[base + j]]);
        acc.x += v.x; acc.y += v.y; acc.z += v.z; acc.w += v.w;
    }
    #pragma unroll
    for (int o = 16; o; o >>= 1) {
        acc.x += __shfl_xor_sync(0xffffffffu, acc.x, o);
        acc.y += __shfl_xor_sync(0xffffffffu, acc.y, o);
        acc.z += __shfl_xor_sync(0xffffffffu, acc.z, o);
        acc.w += __shfl_xor_sync(0xffffffffu, acc.w, o);
    }
    float di = g_dinv[n];
    float4 sv = xs4[n];
    float y0 = di * (acc.x + sv.x);
    float y1 = di * (acc.y + sv.y);
    float y2 = di * (acc.z + sv.z);
    float y3 = di * (acc.w + sv.w);
    float2 b2 = Bs2[lane];
    float a0 = b2.x, a1 = b2.y;
    float2 w0 = Ws2[0 * 32 + lane], w1 = Ws2[1 * 32 + lane];
    float2 w2 = Ws2[2 * 32 + lane], w3 = Ws2[3 * 32 + lane];
    a0 = fmaf(y0, w0.x, a0); a1 = fmaf(y0, w0.y, a1);
    a0 = fmaf(y1, w1.x, a0); a1 = fmaf(y1, w1.y, a1);
    a0 = fmaf(y2, w2.x, a0); a1 = fmaf(y2, w2.y, a1);
    a0 = fmaf(y3, w3.x, a0); a1 = fmaf(y3, w3.y, a1);
    a0 = fmaxf(a0, 0.f);
    a1 = fmaxf(a1, 0.f);
    ((__half2*)g_bufBh)[n * 32 + lane] = __floats2half2_rn(a0, a1);
}

// ------ hidden dense: bufBh(fp16) @ W, pre-scaled by dinv[n] -> bufAh fp16 -----
__global__ void k_gemm64(const float* __restrict__ W) {
    __shared__ float Ws[HID * HID];
    __shared__ __align__(16) float Hs[4 * HID];
    for (int i = threadIdx.x; i < HID * HID; i += blockDim.x) Ws[i] = W[i];
    int nodeBase = blockIdx.x * 64;
    int f  = threadIdx.x & 63;
    int nl = threadIdx.x >> 6;
    for (int c = 0; c < 64; c += 4) {
        __syncthreads();
        int n = nodeBase + c + nl;
        Hs[nl * HID + f] = (n < NN) ? __half2float(g_bufBh[n * HID + f]) : 0.f;
        __syncthreads();
        if (n < NN) {
            const float4* H4 = (const float4*)&Hs[nl * HID];
            float acc = 0.f;
            #pragma unroll
            for (int k4 = 0; k4 < 16; k4++) {
                float4 h = H4[k4];
                acc = fmaf(h.x, Ws[(4 * k4 + 0) * HID + f], acc);
                acc = fmaf(h.y, Ws[(4 * k4 + 1) * HID + f], acc);
                acc = fmaf(h.z, Ws[(4 * k4 + 2) * HID + f], acc);
                acc = fmaf(h.w, Ws[(4 * k4 + 3) * HID + f], acc);
            }
            acc *= g_dinv[n];
            float accHi = __shfl_down_sync(0xffffffffu, acc, 1);
            if ((f & 1) == 0)
                ((__half2*)g_bufAh)[n * 32 + (f >> 1)] = __floats2half2_rn(acc, accHi);
        }
    }
}

// ---- hidden aggregation: warp/node, int4 col batches, half2 gathers ----------
template <bool LAST>
__global__ void k_agg64(const float* __restrict__ bias, const float* __restrict__ Wout) {
    int warp = (blockIdx.x * blockDim.x + threadIdx.x) >> 5;
    int lane = threadIdx.x & 31;
    if (warp >= NN) return;
    int n = warp;
    const __half2* A2 = (const __half2*)g_bufAh;
    float ax = 0.f, ay = 0.f;
    int base = n * MAXD;
    int len = min(g_cnt[n], MAXD);
    int j = 0;
    for (; j + 4 <= len; j += 4) {
        int4 c = *(const int4*)&g_col[base + j];
        float2 v0 = __half22float2(__ldg(&A2[c.x * 32 + lane]));
        float2 v1 = __half22float2(__ldg(&A2[c.y * 32 + lane]));
        float2 v2 = __half22float2(__ldg(&A2[c.z * 32 + lane]));
        float2 v3 = __half22float2(__ldg(&A2[c.w * 32 + lane]));
        ax += v0.x + v1.x + v2.x + v3.x;
        ay += v0.y + v1.y + v2.y + v3.y;
    }
    for (; j < len; j++) {
        int s = g_col[base + j];
        float2 v = __half22float2(__ldg(&A2[s * 32 + lane]));
        ax += v.x;
        ay += v.y;
    }
    float2 sv = __half22float2(A2[n * 32 + lane]);
    ax += sv.x;
    ay += sv.y;
    float di = g_dinv[n];
    float2 b2 = ((const float2*)bias)[lane];
    ax = fmaxf(fmaf(di, ax, b2.x), 0.f);
    ay = fmaxf(fmaf(di, ay, b2.y), 0.f);
    if (!LAST) {
        ((__half2*)g_bufBh)[n * 32 + lane] = __floats2half2_rn(ax, ay);
    } else {
        float2 w2 = ((const float2*)Wout)[lane];
        float s = ax * w2.x + ay * w2.y;
        #pragma unroll
        for (int o = 16; o; o >>= 1) s += __shfl_xor_sync(0xffffffffu, s, o);
        if (lane == 0) g_z[n] = di * s;
    }
}

// ---- final scalar aggregation ------------------------------------------------
__global__ void k_agg_scalar(float* __restrict__ out, const float* __restrict__ b_out) {
    int n = blockIdx.x * blockDim.x + threadIdx.x;
    if (n < NN) {
        float acc = 0.f;
        int base = n * MAXD;
        int len = min(g_cnt[n], MAXD);
        int j = 0;
        for (; j + 4 <= len; j += 4) {
            int4 c = *(const int4*)&g_col[base + j];
            acc += __ldg(&g_z[c.x]) + __ldg(&g_z[c.y]) + __ldg(&g_z[c.z]) + __ldg(&g_z[c.w]);
        }
        for (; j < len; j++) acc += __ldg(&g_z[g_col[base + j]]);
        acc += g_z[n];
        out[n] = fmaf(g_dinv[n], acc, b_out[0]);
    }
}

// ---------------- launch ------------------------------------------------------
extern "C" void kernel_launch(void* const* d_in, const int* in_sizes, int n_in,
                              void* d_out, int out_size) {
    const float* x     = (const float*)d_in[0];
    const int*   ei    = (const int*)d_in[1];
    const float* W_in  = (const float*)d_in[2];
    const float* b_in  = (const float*)d_in[3];
    const float* W_h   = (const float*)d_in[4];
    const float* b_h   = (const float*)d_in[5];
    const float* W_out = (const float*)d_in[6];
    const float* b_out = (const float*)d_in[7];
    float*       out   = (float*)d_out;

    const int TB = 256;
    const int gN  = (NN + TB - 1) / TB;
    const int gE  = (NE + TB - 1) / TB;
    const int gW  = (NN * 32 + TB - 1) / TB;
    const int gG  = (NN + 63) / 64;

    // CSR build (count fused into scatter; no scan)
    k_zero_cnt<<<gN, TB>>>();
    k_scatter_count<<<gE, TB>>>(ei);
    k_dinv_xs<<<gN, TB>>>(x);

    // layer 0 (agg + gemm fused)
    k_aggx_gemm<<<gW, TB>>>(W_in, b_in);

    // hidden layers 1-2
    for (int l = 0; l < 2; l++) {
        k_gemm64<<<gG, TB>>>(W_h + l * HID * HID);
        k_agg64<false><<<gW, TB>>>(b_h + l * HID, nullptr);
    }
    // hidden layer 3 with fused output GEMM
    k_gemm64<<<gG, TB>>>(W_h + 2 * HID * HID);
    k_agg64<true><<<gW, TB>>>(b_h + 2 * HID, W_out);

    // final scalar aggregation
    k_agg_scalar<<<gN, TB>>>(out, b_out);
}

// round 12
// speedup vs baseline: 1.2700x; 1.2007x over previous
#include <cuda_runtime.h>
#include <cuda_fp16.h>
#include <cuda_bf16.h>

#define NN 50000
#define NE 800000
#define HID 64
#define MAXD 128   // per-node bucket capacity (Poisson(16) tail @128 ~ 0)

// ---------------- scratch (device globals; no allocation allowed) -------------
__device__ float   g_xs[NN * 4];       // dinv[n] * x[n]
__device__ __half  g_m0[NN * HID];     // pre-scaled GEMM rows, ping
__device__ __half  g_m1[NN * HID];     // pre-scaled GEMM rows, pong
__device__ float   g_z[NN];            // pre-scaled final scalar
__device__ float   g_dinv[NN];
__device__ int     g_cnt[NN];
__device__ int     g_col[NN * MAXD];   // bucketed CSR (row n at n*MAXD)

// ---------------- CSR build (bucketed: count IS scatter) -----------------------
__global__ void k_zero_cnt() {
    int i = blockIdx.x * blockDim.x + threadIdx.x;
    if (i < NN) g_cnt[i] = 0;
}

__global__ void k_scatter_count(const int* __restrict__ ei) {
    int e = blockIdx.x * blockDim.x + threadIdx.x;
    if (e < NE) {
        int s = ei[e];
        int d = ei[NE + e];
        int pos = atomicAdd(&g_cnt[d], 1);
        if (pos < MAXD) g_col[d * MAXD + pos] = s;
    }
}

__global__ void k_dinv_xs(const float* __restrict__ x) {
    int i = blockIdx.x * blockDim.x + threadIdx.x;
    if (i < NN) {
        float di = rsqrtf((float)(g_cnt[i] + 1));  // +1 self loop
        g_dinv[i] = di;
        float4 v = ((const float4*)x)[i];
        v.x *= di; v.y *= di; v.z *= di; v.w *= di;
        ((float4*)g_xs)[i] = v;
    }
}

// -------- shared helpers: stage W_next into smem; warp GEMM via shuffles -------
// WsA[kl*32+l] = W[2kl][2l..2l+1], WsB[kl*32+l] = W[2kl+1][2l..2l+1]
__device__ __forceinline__ void stage_wnext(const float* __restrict__ Wn,
                                            float2* WsA, float2* WsB, int tid, int nthr) {
    const float2* W2 = (const float2*)Wn;
    for (int i = tid; i < 1024; i += nthr) {
        int kl = i >> 5, l = i & 31;
        WsA[i] = W2[(2 * kl) * 32 + l];
        WsB[i] = W2[(2 * kl + 1) * 32 + l];
    }
}

// lane holds h[2l],h[2l+1]; computes m = dinv*(h@Wn) features 2l,2l+1 -> dst
__device__ __forceinline__ void warp_gemm_store(float ax, float ay, int lane, int n,
                                                float di, const float2* WsA,
                                                const float2* WsB, __half* dst) {
    float m0 = 0.f, m1 = 0.f;
    #pragma unroll
    for (int kl = 0; kl < 32; kl++) {
        float hx = __shfl_sync(0xffffffffu, ax, kl);
        float hy = __shfl_sync(0xffffffffu, ay, kl);
        float2 wa = WsA[kl * 32 + lane];
        float2 wb = WsB[kl * 32 + lane];
        m0 = fmaf(hx, wa.x, m0); m1 = fmaf(hx, wa.y, m1);
        m0 = fmaf(hy, wb.x, m0); m1 = fmaf(hy, wb.y, m1);
    }
    ((__half2*)dst)[n * 32 + lane] = __floats2half2_rn(m0 * di, m1 * di);
}

// ------- layer 0 fused: agg(xs) -> @W_in+b,relu -> @W_h0, prescale -> g_m0 -----
__global__ void k_aggx_gemm(const float* __restrict__ W, const float* __restrict__ bias,
                            const float* __restrict__ Wnext) {
    __shared__ float2 Ws2[4 * 32];
    __shared__ float2 Bs2[32];
    __shared__ float2 WsA[1024];
    __shared__ float2 WsB[1024];
    if (threadIdx.x < 128) {
        int k = threadIdx.x >> 5, l = threadIdx.x & 31;
        Ws2[k * 32 + l] = make_float2(W[k * HID + 2 * l], W[k * HID + 2 * l + 1]);
    }
    if (threadIdx.x < 32)
        Bs2[threadIdx.x] = make_float2(bias[2 * threadIdx.x], bias[2 * threadIdx.x + 1]);
    stage_wnext(Wnext, WsA, WsB, threadIdx.x, blockDim.x);
    __syncthreads();

    int warp = (blockIdx.x * blockDim.x + threadIdx.x) >> 5;
    int lane = threadIdx.x & 31;
    if (warp >= NN) return;
    int n = warp;
    const float4* xs4 = (const float4*)g_xs;
    float4 acc = make_float4(0.f, 0.f, 0.f, 0.f);
    int base = n * MAXD;
    int len = min(g_cnt[n], MAXD);
    for (int j = lane; j < len; j += 32) {
        float4 v = __ldg(&xs4[g_col[base + j]]);
        acc.x += v.x; acc.y += v.y; acc.z += v.z; acc.w += v.w;
    }
    #pragma unroll
    for (int o = 16; o; o >>= 1) {
        acc.x += __shfl_xor_sync(0xffffffffu, acc.x, o);
        acc.y += __shfl_xor_sync(0xffffffffu, acc.y, o);
        acc.z += __shfl_xor_sync(0xffffffffu, acc.z, o);
        acc.w += __shfl_xor_sync(0xffffffffu, acc.w, o);
    }
    float di = g_dinv[n];
    float4 sv = xs4[n];
    float y0 = di * (acc.x + sv.x);
    float y1 = di * (acc.y + sv.y);
    float y2 = di * (acc.z + sv.z);
    float y3 = di * (acc.w + sv.w);
    float2 b2 = Bs2[lane];
    float a0 = b2.x, a1 = b2.y;
    float2 w0 = Ws2[0 * 32 + lane], w1 = Ws2[1 * 32 + lane];
    float2 w2 = Ws2[2 * 32 + lane], w3 = Ws2[3 * 32 + lane];
    a0 = fmaf(y0, w0.x, a0); a1 = fmaf(y0, w0.y, a1);
    a0 = fmaf(y1, w1.x, a0); a1 = fmaf(y1, w1.y, a1);
    a0 = fmaf(y2, w2.x, a0); a1 = fmaf(y2, w2.y, a1);
    a0 = fmaf(y3, w3.x, a0); a1 = fmaf(y3, w3.y, a1);
    a0 = fmaxf(a0, 0.f);
    a1 = fmaxf(a1, 0.f);
    warp_gemm_store(a0, a1, lane, n, di, WsA, WsB, g_m0);
}

// ---- hidden fused: gather src -> h=relu(di*agg+b) -> @Wnext prescale -> dst ---
__global__ void k_agg_gemm(const __half* __restrict__ srcbuf, __half* __restrict__ dstbuf,
                           const float* __restrict__ bias, const float* __restrict__ Wnext) {
    __shared__ float2 Bs2[32];
    __shared__ float2 WsA[1024];
    __shared__ float2 WsB[1024];
    if (threadIdx.x < 32)
        Bs2[threadIdx.x] = make_float2(bias[2 * threadIdx.x], bias[2 * threadIdx.x + 1]);
    stage_wnext(Wnext, WsA, WsB, threadIdx.x, blockDim.x);
    __syncthreads();

    int warp = (blockIdx.x * blockDim.x + threadIdx.x) >> 5;
    int lane = threadIdx.x & 31;
    if (warp >= NN) return;
    int n = warp;
    const __half2* A2 = (const __half2*)srcbuf;
    float ax = 0.f, ay = 0.f;
    int base = n * MAXD;
    int len = min(g_cnt[n], MAXD);
    int j = 0;
    for (; j + 4 <= len; j += 4) {
        int4 c = *(const int4*)&g_col[base + j];
        float2 v0 = __half22float2(__ldg(&A2[c.x * 32 + lane]));
        float2 v1 = __half22float2(__ldg(&A2[c.y * 32 + lane]));
        float2 v2 = __half22float2(__ldg(&A2[c.z * 32 + lane]));
        float2 v3 = __half22float2(__ldg(&A2[c.w * 32 + lane]));
        ax += v0.x + v1.x + v2.x + v3.x;
        ay += v0.y + v1.y + v2.y + v3.y;
    }
    for (; j < len; j++) {
        int s = g_col[base + j];
        float2 v = __half22float2(__ldg(&A2[s * 32 + lane]));
        ax += v.x;
        ay += v.y;
    }
    float2 sv = __half22float2(A2[n * 32 + lane]);
    ax += sv.x;
    ay += sv.y;
    float di = g_dinv[n];
    float2 b2 = Bs2[lane];
    ax = fmaxf(fmaf(di, ax, b2.x), 0.f);
    ay = fmaxf(fmaf(di, ay, b2.y), 0.f);
    warp_gemm_store(ax, ay, lane, n, di, WsA, WsB, dstbuf);
}

// ---- last hidden layer: gather -> h=relu(di*agg+b) -> z = di*(h.Wout) ---------
__global__ void k_agg_last(const __half* __restrict__ srcbuf,
                           const float* __restrict__ bias, const float* __restrict__ Wout) {
    int warp = (blockIdx.x * blockDim.x + threadIdx.x) >> 5;
    int lane = threadIdx.x & 31;
    if (warp >= NN) return;
    int n = warp;
    const __half2* A2 = (const __half2*)srcbuf;
    float ax = 0.f, ay = 0.f;
    int base = n * MAXD;
    int len = min(g_cnt[n], MAXD);
    int j = 0;
    for (; j + 4 <= len; j += 4) {
        int4 c = *(const int4*)&g_col[base + j];
        float2 v0 = __half22float2(__ldg(&A2[c.x * 32 + lane]));
        float2 v1 = __half22float2(__ldg(&A2[c.y * 32 + lane]));
        float2 v2 = __half22float2(__ldg(&A2[c.z * 32 + lane]));
        float2 v3 = __half22float2(__ldg(&A2[c.w * 32 + lane]));
        ax += v0.x + v1.x + v2.x + v3.x;
        ay += v0.y + v1.y + v2.y + v3.y;
    }
    for (; j < len; j++) {
        int s = g_col[base + j];
        float2 v = __half22float2(__ldg(&A2[s * 32 + lane]));
        ax += v.x;
        ay += v.y;
    }
    float2 sv = __half22float2(A2[n * 32 + lane]);
    ax += sv.x;
    ay += sv.y;
    float di = g_dinv[n];
    float2 b2 = ((const float2*)bias)[lane];
    ax = fmaxf(fmaf(di, ax, b2.x), 0.f);
    ay = fmaxf(fmaf(di, ay, b2.y), 0.f);
    float2 w2 = ((const float2*)Wout)[lane];
    float s = ax * w2.x + ay * w2.y;
    #pragma unroll
    for (int o = 16; o; o >>= 1) s += __shfl_xor_sync(0xffffffffu, s, o);
    if (lane == 0) g_z[n] = di * s;
}

// ---- final scalar aggregation ------------------------------------------------
__global__ void k_agg_scalar(float* __restrict__ out, const float* __restrict__ b_out) {
    int n = blockIdx.x * blockDim.x + threadIdx.x;
    if (n < NN) {
        float acc = 0.f;
        int base = n * MAXD;
        int len = min(g_cnt[n], MAXD);
        int j = 0;
        for (; j + 4 <= len; j += 4) {
            int4 c = *(const int4*)&g_col[base + j];
            acc += __ldg(&g_z[c.x]) + __ldg(&g_z[c.y]) + __ldg(&g_z[c.z]) + __ldg(&g_z[c.w]);
        }
        for (; j < len; j++) acc += __ldg(&g_z[g_col[base + j]]);
        acc += g_z[n];
        out[n] = fmaf(g_dinv[n], acc, b_out[0]);
    }
}

// ---------------- launch ------------------------------------------------------
extern "C" void kernel_launch(void* const* d_in, const int* in_sizes, int n_in,
                              void* d_out, int out_size) {
    const float* x     = (const float*)d_in[0];
    const int*   ei    = (const int*)d_in[1];
    const float* W_in  = (const float*)d_in[2];
    const float* b_in  = (const float*)d_in[3];
    const float* W_h   = (const float*)d_in[4];
    const float* b_h   = (const float*)d_in[5];
    const float* W_out = (const float*)d_in[6];
    const float* b_out = (const float*)d_in[7];
    float*       out   = (float*)d_out;

    const int TB = 256;
    const int gN  = (NN + TB - 1) / TB;
    const int gE  = (NE + TB - 1) / TB;
    const int gW  = (NN * 32 + TB - 1) / TB;

    __half* m0; cudaGetSymbolAddress((void**)&m0, g_m0);
    __half* m1; cudaGetSymbolAddress((void**)&m1, g_m1);

    // CSR build
    k_zero_cnt<<<gN, TB>>>();
    k_scatter_count<<<gE, TB>>>(ei);
    k_dinv_xs<<<gN, TB>>>(x);

    // layer 0: agg(x) -> @W_in+b_in,relu -> @W_h[0] prescaled -> m0
    k_aggx_gemm<<<gW, TB>>>(W_in, b_in, W_h + 0 * HID * HID);

    // hidden: m0 -> (agg,b_h0-relu? NO: bias pairing) ...
    // h2 = relu(agg(m0)+b_h[0]) -> @W_h[1] -> m1
    k_agg_gemm<<<gW, TB>>>(m0, m1, b_h + 0 * HID, W_h + 1 * HID * HID);
    // h3 = relu(agg(m1)+b_h[1]) -> @W_h[2] -> m0
    k_agg_gemm<<<gW, TB>>>(m1, m0, b_h + 1 * HID, W_h + 2 * HID * HID);
    // h4 = relu(agg(m0)+b_h[2]) -> z = di*(h4 . W_out)
    k_agg_last<<<gW, TB>>>(m0, b_h + 2 * HID, W_out);

    // out = di*(sum z + z_self) + b_out
    k_agg_scalar<<<gN, TB>>>(out, b_out);
}

// round 13
// speedup vs baseline: 1.5357x; 1.2092x over previous
#include <cuda_runtime.h>
#include <cuda_fp16.h>
#include <cuda_bf16.h>

#define NN 50000
#define NE 800000
#define HID 64
#define MAXD 128   // per-node bucket capacity (Poisson(16) tail @128 ~ 0)

// ---------------- scratch (device globals; no allocation allowed) -------------
__device__ float   g_xs[NN * 4];       // dinv[n] * x[n]
__device__ __half  g_m0[NN * HID];     // pre-scaled GEMM rows, ping
__device__ __half  g_m1[NN * HID];     // pre-scaled GEMM rows, pong
__device__ float   g_z[NN];            // pre-scaled final scalar
__device__ float   g_dinv[NN];
__device__ int     g_cnt[NN];
__device__ int     g_col[NN * MAXD];   // bucketed CSR (row n at n*MAXD)

// ---------------- CSR build (bucketed: count IS scatter) -----------------------
__global__ void k_zero_cnt() {
    int i = blockIdx.x * blockDim.x + threadIdx.x;
    if (i < NN) g_cnt[i] = 0;
}

__global__ void k_scatter_count(const int* __restrict__ ei) {
    int e = blockIdx.x * blockDim.x + threadIdx.x;
    if (e < NE) {
        int s = ei[e];
        int d = ei[NE + e];
        int pos = atomicAdd(&g_cnt[d], 1);
        if (pos < MAXD) g_col[d * MAXD + pos] = s;
    }
}

__global__ void k_dinv_xs(const float* __restrict__ x) {
    int i = blockIdx.x * blockDim.x + threadIdx.x;
    if (i < NN) {
        float di = rsqrtf((float)(g_cnt[i] + 1));  // +1 self loop
        g_dinv[i] = di;
        float4 v = ((const float4*)x)[i];
        v.x *= di; v.y *= di; v.z *= di; v.w *= di;
        ((float4*)g_xs)[i] = v;
    }
}

// ---- shared helpers: stage W_next as packed fp16; warp GEMM via shuffles ------
// Wc[kl*32+l] = uint2{ half2(W[2kl][2l],W[2kl][2l+1]), half2(W[2kl+1][2l],W[2kl+1][2l+1]) }
__device__ __forceinline__ void stage_wnext(const float* __restrict__ Wn,
                                            uint2* Wc, int tid, int nthr) {
    const float2* W2 = (const float2*)Wn;
    for (int i = tid; i < 1024; i += nthr) {
        int kl = i >> 5, l = i & 31;
        float2 a = W2[(2 * kl) * 32 + l];
        float2 b = W2[(2 * kl + 1) * 32 + l];
        __half2 ha = __floats2half2_rn(a.x, a.y);
        __half2 hb = __floats2half2_rn(b.x, b.y);
        uint2 w;
        w.x = *(unsigned int*)&ha;
        w.y = *(unsigned int*)&hb;
        Wc[i] = w;
    }
}

// lane holds h[2l],h[2l+1]; computes m = dinv*(h@Wn) features 2l,2l+1 -> dst
__device__ __forceinline__ void warp_gemm_store(float ax, float ay, int lane, int n,
                                                float di, const uint2* Wc, __half* dst) {
    float m0 = 0.f, m1 = 0.f;
    #pragma unroll
    for (int kl = 0; kl < 32; kl++) {
        float hx = __shfl_sync(0xffffffffu, ax, kl);
        float hy = __shfl_sync(0xffffffffu, ay, kl);
        uint2 w = Wc[kl * 32 + lane];
        float2 wa = __half22float2(*(__half2*)&w.x);
        float2 wb = __half22float2(*(__half2*)&w.y);
        m0 = fmaf(hx, wa.x, m0); m1 = fmaf(hx, wa.y, m1);
        m0 = fmaf(hy, wb.x, m0); m1 = fmaf(hy, wb.y, m1);
    }
    ((__half2*)dst)[n * 32 + lane] = __floats2half2_rn(m0 * di, m1 * di);
}

// ------- layer 0 fused: agg(xs) -> @W_in+b,relu -> @W_h0, prescale -> g_m0 -----
__global__ void k_aggx_gemm(const float* __restrict__ W, const float* __restrict__ bias,
                            const float* __restrict__ Wnext) {
    __shared__ float2 Ws2[4 * 32];
    __shared__ float2 Bs2[32];
    __shared__ uint2 Wc[1024];
    if (threadIdx.x < 128) {
        int k = threadIdx.x >> 5, l = threadIdx.x & 31;
        Ws2[k * 32 + l] = make_float2(W[k * HID + 2 * l], W[k * HID + 2 * l + 1]);
    }
    if (threadIdx.x < 32)
        Bs2[threadIdx.x] = make_float2(bias[2 * threadIdx.x], bias[2 * threadIdx.x + 1]);
    stage_wnext(Wnext, Wc, threadIdx.x, blockDim.x);
    __syncthreads();

    int warp = (blockIdx.x * blockDim.x + threadIdx.x) >> 5;
    int lane = threadIdx.x & 31;
    if (warp >= NN) return;
    int n = warp;
    const float4* xs4 = (const float4*)g_xs;
    float4 acc = make_float4(0.f, 0.f, 0.f, 0.f);
    int base = n * MAXD;
    int len = min(g_cnt[n], MAXD);
    for (int j = lane; j < len; j += 32) {
        float4 v = __ldg(&xs4[g_col[base + j]]);
        acc.x += v.x; acc.y += v.y; acc.z += v.z; acc.w += v.w;
    }
    #pragma unroll
    for (int o = 16; o; o >>= 1) {
        acc.x += __shfl_xor_sync(0xffffffffu, acc.x, o);
        acc.y += __shfl_xor_sync(0xffffffffu, acc.y, o);
        acc.z += __shfl_xor_sync(0xffffffffu, acc.z, o);
        acc.w += __shfl_xor_sync(0xffffffffu, acc.w, o);
    }
    float di = g_dinv[n];
    float4 sv = xs4[n];
    float y0 = di * (acc.x + sv.x);
    float y1 = di * (acc.y + sv.y);
    float y2 = di * (acc.z + sv.z);
    float y3 = di * (acc.w + sv.w);
    float2 b2 = Bs2[lane];
    float a0 = b2.x, a1 = b2.y;
    float2 w0 = Ws2[0 * 32 + lane], w1 = Ws2[1 * 32 + lane];
    float2 w2 = Ws2[2 * 32 + lane], w3 = Ws2[3 * 32 + lane];
    a0 = fmaf(y0, w0.x, a0); a1 = fmaf(y0, w0.y, a1);
    a0 = fmaf(y1, w1.x, a0); a1 = fmaf(y1, w1.y, a1);
    a0 = fmaf(y2, w2.x, a0); a1 = fmaf(y2, w2.y, a1);
    a0 = fmaf(y3, w3.x, a0); a1 = fmaf(y3, w3.y, a1);
    a0 = fmaxf(a0, 0.f);
    a1 = fmaxf(a1, 0.f);
    warp_gemm_store(a0, a1, lane, n, di, Wc, g_m0);
}

// ---- hidden fused: gather src -> h=relu(di*agg+b) -> @Wnext prescale -> dst ---
__global__ void k_agg_gemm(const __half* __restrict__ srcbuf, __half* __restrict__ dstbuf,
                           const float* __restrict__ bias, const float* __restrict__ Wnext) {
    __shared__ float2 Bs2[32];
    __shared__ uint2 Wc[1024];
    if (threadIdx.x < 32)
        Bs2[threadIdx.x] = make_float2(bias[2 * threadIdx.x], bias[2 * threadIdx.x + 1]);
    stage_wnext(Wnext, Wc, threadIdx.x, blockDim.x);
    __syncthreads();

    int warp = (blockIdx.x * blockDim.x + threadIdx.x) >> 5;
    int lane = threadIdx.x & 31;
    if (warp >= NN) return;
    int n = warp;
    const __half2* A2 = (const __half2*)srcbuf;
    float ax = 0.f, ay = 0.f;
    int base = n * MAXD;
    int len = min(g_cnt[n], MAXD);
    int j = 0;
    for (; j + 4 <= len; j += 4) {
        int4 c = *(const int4*)&g_col[base + j];
        float2 v0 = __half22float2(__ldg(&A2[c.x * 32 + lane]));
        float2 v1 = __half22float2(__ldg(&A2[c.y * 32 + lane]));
        float2 v2 = __half22float2(__ldg(&A2[c.z * 32 + lane]));
        float2 v3 = __half22float2(__ldg(&A2[c.w * 32 + lane]));
        ax += v0.x + v1.x + v2.x + v3.x;
        ay += v0.y + v1.y + v2.y + v3.y;
    }
    for (; j < len; j++) {
        int s = g_col[base + j];
        float2 v = __half22float2(__ldg(&A2[s * 32 + lane]));
        ax += v.x;
        ay += v.y;
    }
    float2 sv = __half22float2(A2[n * 32 + lane]);
    ax += sv.x;
    ay += sv.y;
    float di = g_dinv[n];
    float2 b2 = Bs2[lane];
    ax = fmaxf(fmaf(di, ax, b2.x), 0.f);
    ay = fmaxf(fmaf(di, ay, b2.y), 0.f);
    warp_gemm_store(ax, ay, lane, n, di, Wc, dstbuf);
}

// ---- last hidden layer: gather -> h=relu(di*agg+b) -> z = di*(h.Wout) ---------
__global__ void k_agg_last(const __half* __restrict__ srcbuf,
                           const float* __restrict__ bias, const float* __restrict__ Wout) {
    int warp = (blockIdx.x * blockDim.x + threadIdx.x) >> 5;
    int lane = threadIdx.x & 31;
    if (warp >= NN) return;
    int n = warp;
    const __half2* A2 = (const __half2*)srcbuf;
    float ax = 0.f, ay = 0.f;
    int base = n * MAXD;
    int len = min(g_cnt[n], MAXD);
    int j = 0;
    for (; j + 4 <= len; j += 4) {
        int4 c = *(const int4*)&g_col[base + j];
        float2 v0 = __half22float2(__ldg(&A2[c.x * 32 + lane]));
        float2 v1 = __half22float2(__ldg(&A2[c.y * 32 + lane]));
        float2 v2 = __half22float2(__ldg(&A2[c.z * 32 + lane]));
        float2 v3 = __half22float2(__ldg(&A2[c.w * 32 + lane]));
        ax += v0.x + v1.x + v2.x + v3.x;
        ay += v0.y + v1.y + v2.y + v3.y;
    }
    for (; j < len; j++) {
        int s = g_col[base + j];
        float2 v = __half22float2(__ldg(&A2[s * 32 + lane]));
        ax += v.x;
        ay += v.y;
    }
    float2 sv = __half22float2(A2[n * 32 + lane]);
    ax += sv.x;
    ay += sv.y;
    float di = g_dinv[n];
    float2 b2 = ((const float2*)bias)[lane];
    ax = fmaxf(fmaf(di, ax, b2.x), 0.f);
    ay = fmaxf(fmaf(di, ay, b2.y), 0.f);
    float2 w2 = ((const float2*)Wout)[lane];
    float s = ax * w2.x + ay * w2.y;
    #pragma unroll
    for (int o = 16; o; o >>= 1) s += __shfl_xor_sync(0xffffffffu, s, o);
    if (lane == 0) g_z[n] = di * s;
}

// ---- final scalar aggregation ------------------------------------------------
__global__ void k_agg_scalar(float* __restrict__ out, const float* __restrict__ b_out) {
    int n = blockIdx.x * blockDim.x + threadIdx.x;
    if (n < NN) {
        float acc = 0.f;
        int base = n * MAXD;
        int len = min(g_cnt[n], MAXD);
        int j = 0;
        for (; j + 4 <= len; j += 4) {
            int4 c = *(const int4*)&g_col[base + j];
            acc += __ldg(&g_z[c.x]) + __ldg(&g_z[c.y]) + __ldg(&g_z[c.z]) + __ldg(&g_z[c.w]);
        }
        for (; j < len; j++) acc += __ldg(&g_z[g_col[base + j]]);
        acc += g_z[n];
        out[n] = fmaf(g_dinv[n], acc, b_out[0]);
    }
}

// ---------------- launch ------------------------------------------------------
extern "C" void kernel_launch(void* const* d_in, const int* in_sizes, int n_in,
                              void* d_out, int out_size) {
    const float* x     = (const float*)d_in[0];
    const int*   ei    = (const int*)d_in[1];
    const float* W_in  = (const float*)d_in[2];
    const float* b_in  = (const float*)d_in[3];
    const float* W_h   = (const float*)d_in[4];
    const float* b_h   = (const float*)d_in[5];
    const float* W_out = (const float*)d_in[6];
    const float* b_out = (const float*)d_in[7];
    float*       out   = (float*)d_out;

    const int TB = 256;
    const int gN  = (NN + TB - 1) / TB;
    const int gE  = (NE + TB - 1) / TB;
    const int gW  = (NN * 32 + TB - 1) / TB;

    __half* m0; cudaGetSymbolAddress((void**)&m0, g_m0);
    __half* m1; cudaGetSymbolAddress((void**)&m1, g_m1);

    // CSR build
    k_zero_cnt<<<gN, TB>>>();
    k_scatter_count<<<gE, TB>>>(ei);
    k_dinv_xs<<<gN, TB>>>(x);

    // layer 0: agg(x) -> @W_in+b_in,relu -> @W_h[0] prescaled -> m0
    k_aggx_gemm<<<gW, TB>>>(W_in, b_in, W_h + 0 * HID * HID);

    // h2 = relu(agg(m0)+b_h[0]) -> @W_h[1] -> m1
    k_agg_gemm<<<gW, TB>>>(m0, m1, b_h + 0 * HID, W_h + 1 * HID * HID);
    // h3 = relu(agg(m1)+b_h[1]) -> @W_h[2] -> m0
    k_agg_gemm<<<gW, TB>>>(m1, m0, b_h + 1 * HID, W_h + 2 * HID * HID);
    // h4 = relu(agg(m0)+b_h[2]) -> z = di*(h4 . W_out)
    k_agg_last<<<gW, TB>>>(m0, b_h + 2 * HID, W_out);

    // out = di*(sum z + z_self) + b_out
    k_agg_scalar<<<gN, TB>>>(out, b_out);
}

// round 14
// speedup vs baseline: 1.7950x; 1.1688x over previous
#include <cuda_runtime.h>
#include <cuda_fp16.h>
#include <cuda_bf16.h>

#define NN 50000
#define NE 800000
#define HID 64
#define MAXD 128   // per-node bucket capacity (Poisson(16) tail @128 ~ 0)
#define NPW 4      // nodes per warp in fused agg+gemm kernels (NN % 4 == 0)

// ---------------- scratch (device globals; no allocation allowed) -------------
__device__ float   g_xs[NN * 4];       // dinv[n] * x[n]
__device__ __half  g_m0[NN * HID];     // pre-scaled GEMM rows, ping
__device__ __half  g_m1[NN * HID];     // pre-scaled GEMM rows, pong
__device__ float   g_z[NN];            // pre-scaled final scalar
__device__ float   g_dinv[NN];
__device__ int     g_cnt[NN];
__device__ int     g_col[NN * MAXD];   // bucketed CSR (row n at n*MAXD)

// ---------------- CSR build (bucketed: count IS scatter) -----------------------
__global__ void k_zero_cnt() {
    int i = blockIdx.x * blockDim.x + threadIdx.x;
    if (i < NN) g_cnt[i] = 0;
}

__global__ void k_scatter_count(const int* __restrict__ ei) {
    int e = blockIdx.x * blockDim.x + threadIdx.x;
    if (e < NE) {
        int s = ei[e];
        int d = ei[NE + e];
        int pos = atomicAdd(&g_cnt[d], 1);
        if (pos < MAXD) g_col[d * MAXD + pos] = s;
    }
}

__global__ void k_dinv_xs(const float* __restrict__ x) {
    int i = blockIdx.x * blockDim.x + threadIdx.x;
    if (i < NN) {
        float di = rsqrtf((float)(g_cnt[i] + 1));  // +1 self loop
        g_dinv[i] = di;
        float4 v = ((const float4*)x)[i];
        v.x *= di; v.y *= di; v.z *= di; v.w *= di;
        ((float4*)g_xs)[i] = v;
    }
}

// ---- stage W_next as packed fp16 ---------------------------------------------
// Wc[kl*32+l] = uint2{ half2(W[2kl][2l..2l+1]), half2(W[2kl+1][2l..2l+1]) }
__device__ __forceinline__ void stage_wnext(const float* __restrict__ Wn,
                                            uint2* Wc, int tid, int nthr) {
    const float2* W2 = (const float2*)Wn;
    for (int i = tid; i < 1024; i += nthr) {
        int kl = i >> 5, l = i & 31;
        float2 a = W2[(2 * kl) * 32 + l];
        float2 b = W2[(2 * kl + 1) * 32 + l];
        __half2 ha = __floats2half2_rn(a.x, a.y);
        __half2 hb = __floats2half2_rn(b.x, b.y);
        uint2 w;
        w.x = *(unsigned int*)&ha;
        w.y = *(unsigned int*)&hb;
        Wc[i] = w;
    }
}

// ---- per-node fp16 gather with 8-deep MLP, returns (ax, ay) for lane features -
__device__ __forceinline__ void gather16(const __half2* __restrict__ A2, int n, int lane,
                                         float& axo, float& ayo) {
    float ax = 0.f, ay = 0.f;
    int base = n * MAXD;
    int len = min(g_cnt[n], MAXD);
    int j = 0;
    for (; j + 8 <= len; j += 8) {
        int4 c0 = *(const int4*)&g_col[base + j];
        int4 c1 = *(const int4*)&g_col[base + j + 4];
        __half2 v0 = __ldg(&A2[c0.x * 32 + lane]);
        __half2 v1 = __ldg(&A2[c0.y * 32 + lane]);
        __half2 v2 = __ldg(&A2[c0.z * 32 + lane]);
        __half2 v3 = __ldg(&A2[c0.w * 32 + lane]);
        __half2 v4 = __ldg(&A2[c1.x * 32 + lane]);
        __half2 v5 = __ldg(&A2[c1.y * 32 + lane]);
        __half2 v6 = __ldg(&A2[c1.z * 32 + lane]);
        __half2 v7 = __ldg(&A2[c1.w * 32 + lane]);
        float2 f0 = __half22float2(v0), f1 = __half22float2(v1);
        float2 f2 = __half22float2(v2), f3 = __half22float2(v3);
        float2 f4 = __half22float2(v4), f5 = __half22float2(v5);
        float2 f6 = __half22float2(v6), f7 = __half22float2(v7);
        ax += (f0.x + f1.x) + (f2.x + f3.x) + (f4.x + f5.x) + (f6.x + f7.x);
        ay += (f0.y + f1.y) + (f2.y + f3.y) + (f4.y + f5.y) + (f6.y + f7.y);
    }
    for (; j + 4 <= len; j += 4) {
        int4 c = *(const int4*)&g_col[base + j];
        float2 f0 = __half22float2(__ldg(&A2[c.x * 32 + lane]));
        float2 f1 = __half22float2(__ldg(&A2[c.y * 32 + lane]));
        float2 f2 = __half22float2(__ldg(&A2[c.z * 32 + lane]));
        float2 f3 = __half22float2(__ldg(&A2[c.w * 32 + lane]));
        ax += (f0.x + f1.x) + (f2.x + f3.x);
        ay += (f0.y + f1.y) + (f2.y + f3.y);
    }
    for (; j < len; j++) {
        float2 f = __half22float2(__ldg(&A2[g_col[base + j] * 32 + lane]));
        ax += f.x;
        ay += f.y;
    }
    float2 sv = __half22float2(A2[n * 32 + lane]);
    axo = ax + sv.x;
    ayo = ay + sv.y;
}

// ------- layer 0 fused, NPW nodes/warp: agg(xs) -> W_in+b,relu -> @W_h0 --------
__global__ void k_aggx_gemm(const float* __restrict__ W, const float* __restrict__ bias,
                            const float* __restrict__ Wnext) {
    __shared__ float2 Ws2[4 * 32];
    __shared__ float2 Bs2[32];
    __shared__ uint2 Wc[1024];
    if (threadIdx.x < 128) {
        int k = threadIdx.x >> 5, l = threadIdx.x & 31;
        Ws2[k * 32 + l] = make_float2(W[k * HID + 2 * l], W[k * HID + 2 * l + 1]);
    }
    if (threadIdx.x < 32)
        Bs2[threadIdx.x] = make_float2(bias[2 * threadIdx.x], bias[2 * threadIdx.x + 1]);
    stage_wnext(Wnext, Wc, threadIdx.x, blockDim.x);
    __syncthreads();

    int warp = (blockIdx.x * blockDim.x + threadIdx.x) >> 5;
    int lane = threadIdx.x & 31;
    int n0 = warp * NPW;
    if (n0 >= NN) return;
    const float4* xs4 = (const float4*)g_xs;

    float hx[NPW], hy[NPW];
    #pragma unroll
    for (int i = 0; i < NPW; i++) {
        int n = n0 + i;
        float4 acc = make_float4(0.f, 0.f, 0.f, 0.f);
        int base = n * MAXD;
        int len = min(g_cnt[n], MAXD);
        for (int j = lane; j < len; j += 32) {
            float4 v = __ldg(&xs4[g_col[base + j]]);
            acc.x += v.x; acc.y += v.y; acc.z += v.z; acc.w += v.w;
        }
        #pragma unroll
        for (int o = 16; o; o >>= 1) {
            acc.x += __shfl_xor_sync(0xffffffffu, acc.x, o);
            acc.y += __shfl_xor_sync(0xffffffffu, acc.y, o);
            acc.z += __shfl_xor_sync(0xffffffffu, acc.z, o);
            acc.w += __shfl_xor_sync(0xffffffffu, acc.w, o);
        }
        float di = g_dinv[n];
        float4 sv = xs4[n];
        float y0 = di * (acc.x + sv.x);
        float y1 = di * (acc.y + sv.y);
        float y2 = di * (acc.z + sv.z);
        float y3 = di * (acc.w + sv.w);
        float2 b2 = Bs2[lane];
        float a0 = b2.x, a1 = b2.y;
        float2 w0 = Ws2[0 * 32 + lane], w1 = Ws2[1 * 32 + lane];
        float2 w2 = Ws2[2 * 32 + lane], w3 = Ws2[3 * 32 + lane];
        a0 = fmaf(y0, w0.x, a0); a1 = fmaf(y0, w0.y, a1);
        a0 = fmaf(y1, w1.x, a0); a1 = fmaf(y1, w1.y, a1);
        a0 = fmaf(y2, w2.x, a0); a1 = fmaf(y2, w2.y, a1);
        a0 = fmaf(y3, w3.x, a0); a1 = fmaf(y3, w3.y, a1);
        hx[i] = fmaxf(a0, 0.f);
        hy[i] = fmaxf(a1, 0.f);
    }

    float mA[NPW], mB[NPW];
    #pragma unroll
    for (int i = 0; i < NPW; i++) { mA[i] = 0.f; mB[i] = 0.f; }
    #pragma unroll
    for (int kl = 0; kl < 32; kl++) {
        uint2 w = Wc[kl * 32 + lane];
        float2 wa = __half22float2(*(__half2*)&w.x);
        float2 wb = __half22float2(*(__half2*)&w.y);
        #pragma unroll
        for (int i = 0; i < NPW; i++) {
            float sx = __shfl_sync(0xffffffffu, hx[i], kl);
            float sy = __shfl_sync(0xffffffffu, hy[i], kl);
            mA[i] = fmaf(sx, wa.x, mA[i]); mB[i] = fmaf(sx, wa.y, mB[i]);
            mA[i] = fmaf(sy, wb.x, mA[i]); mB[i] = fmaf(sy, wb.y, mB[i]);
        }
    }
    #pragma unroll
    for (int i = 0; i < NPW; i++) {
        int n = n0 + i;
        float di = g_dinv[n];
        ((__half2*)g_m0)[n * 32 + lane] = __floats2half2_rn(mA[i] * di, mB[i] * di);
    }
}

// ---- hidden fused, NPW nodes/warp: gather -> relu(di*agg+b) -> @Wnext ---------
__global__ void k_agg_gemm(const __half* __restrict__ srcbuf, __half* __restrict__ dstbuf,
                           const float* __restrict__ bias, const float* __restrict__ Wnext) {
    __shared__ float2 Bs2[32];
    __shared__ uint2 Wc[1024];
    if (threadIdx.x < 32)
        Bs2[threadIdx.x] = make_float2(bias[2 * threadIdx.x], bias[2 * threadIdx.x + 1]);
    stage_wnext(Wnext, Wc, threadIdx.x, blockDim.x);
    __syncthreads();

    int warp = (blockIdx.x * blockDim.x + threadIdx.x) >> 5;
    int lane = threadIdx.x & 31;
    int n0 = warp * NPW;
    if (n0 >= NN) return;
    const __half2* A2 = (const __half2*)srcbuf;

    float hx[NPW], hy[NPW];
    #pragma unroll
    for (int i = 0; i < NPW; i++) {
        int n = n0 + i;
        float ax, ay;
        gather16(A2, n, lane, ax, ay);
        float di = g_dinv[n];
        float2 b2 = Bs2[lane];
        hx[i] = fmaxf(fmaf(di, ax, b2.x), 0.f);
        hy[i] = fmaxf(fmaf(di, ay, b2.y), 0.f);
    }

    float mA[NPW], mB[NPW];
    #pragma unroll
    for (int i = 0; i < NPW; i++) { mA[i] = 0.f; mB[i] = 0.f; }
    #pragma unroll
    for (int kl = 0; kl < 32; kl++) {
        uint2 w = Wc[kl * 32 + lane];
        float2 wa = __half22float2(*(__half2*)&w.x);
        float2 wb = __half22float2(*(__half2*)&w.y);
        #pragma unroll
        for (int i = 0; i < NPW; i++) {
            float sx = __shfl_sync(0xffffffffu, hx[i], kl);
            float sy = __shfl_sync(0xffffffffu, hy[i], kl);
            mA[i] = fmaf(sx, wa.x, mA[i]); mB[i] = fmaf(sx, wa.y, mB[i]);
            mA[i] = fmaf(sy, wb.x, mA[i]); mB[i] = fmaf(sy, wb.y, mB[i]);
        }
    }
    #pragma unroll
    for (int i = 0; i < NPW; i++) {
        int n = n0 + i;
        float di = g_dinv[n];
        ((__half2*)dstbuf)[n * 32 + lane] = __floats2half2_rn(mA[i] * di, mB[i] * di);
    }
}

// ---- last hidden layer: gather -> h=relu(di*agg+b) -> z = di*(h.Wout) ---------
__global__ void k_agg_last(const __half* __restrict__ srcbuf,
                           const float* __restrict__ bias, const float* __restrict__ Wout) {
    int warp = (blockIdx.x * blockDim.x + threadIdx.x) >> 5;
    int lane = threadIdx.x & 31;
    if (warp >= NN) return;
    int n = warp;
    const __half2* A2 = (const __half2*)srcbuf;
    float ax, ay;
    gather16(A2, n, lane, ax, ay);
    float di = g_dinv[n];
    float2 b2 = ((const float2*)bias)[lane];
    ax = fmaxf(fmaf(di, ax, b2.x), 0.f);
    ay = fmaxf(fmaf(di, ay, b2.y), 0.f);
    float2 w2 = ((const float2*)Wout)[lane];
    float s = ax * w2.x + ay * w2.y;
    #pragma unroll
    for (int o = 16; o; o >>= 1) s += __shfl_xor_sync(0xffffffffu, s, o);
    if (lane == 0) g_z[n] = di * s;
}

// ---- final scalar aggregation ------------------------------------------------
__global__ void k_agg_scalar(float* __restrict__ out, const float* __restrict__ b_out) {
    int n = blockIdx.x * blockDim.x + threadIdx.x;
    if (n < NN) {
        float acc = 0.f;
        int base = n * MAXD;
        int len = min(g_cnt[n], MAXD);
        int j = 0;
        for (; j + 8 <= len; j += 8) {
            int4 c0 = *(const int4*)&g_col[base + j];
            int4 c1 = *(const int4*)&g_col[base + j + 4];
            float z0 = __ldg(&g_z[c0.x]), z1 = __ldg(&g_z[c0.y]);
            float z2 = __ldg(&g_z[c0.z]), z3 = __ldg(&g_z[c0.w]);
            float z4 = __ldg(&g_z[c1.x]), z5 = __ldg(&g_z[c1.y]);
            float z6 = __ldg(&g_z[c1.z]), z7 = __ldg(&g_z[c1.w]);
            acc += (z0 + z1) + (z2 + z3) + (z4 + z5) + (z6 + z7);
        }
        for (; j + 4 <= len; j += 4) {
            int4 c = *(const int4*)&g_col[base + j];
            acc += __ldg(&g_z[c.x]) + __ldg(&g_z[c.y]) + __ldg(&g_z[c.z]) + __ldg(&g_z[c.w]);
        }
        for (; j < len; j++) acc += __ldg(&g_z[g_col[base + j]]);
        acc += g_z[n];
        out[n] = fmaf(g_dinv[n], acc, b_out[0]);
    }
}

// ---------------- launch ------------------------------------------------------
extern "C" void kernel_launch(void* const* d_in, const int* in_sizes, int n_in,
                              void* d_out, int out_size) {
    const float* x     = (const float*)d_in[0];
    const int*   ei    = (const int*)d_in[1];
    const float* W_in  = (const float*)d_in[2];
    const float* b_in  = (const float*)d_in[3];
    const float* W_h   = (const float*)d_in[4];
    const float* b_h   = (const float*)d_in[5];
    const float* W_out = (const float*)d_in[6];
    const float* b_out = (const float*)d_in[7];
    float*       out   = (float*)d_out;

    const int TB = 256;
    const int gN  = (NN + TB - 1) / TB;
    const int gE  = (NE + TB - 1) / TB;
    const int gW  = (NN * 32 + TB - 1) / TB;                      // warp per node
    const int nWarp4 = (NN + NPW - 1) / NPW;                      // 12500
    const int gW4 = (nWarp4 * 32 + TB - 1) / TB;                  // fused kernels

    __half* m0; cudaGetSymbolAddress((void**)&m0, g_m0);
    __half* m1; cudaGetSymbolAddress((void**)&m1, g_m1);

    // CSR build
    k_zero_cnt<<<gN, TB>>>();
    k_scatter_count<<<gE, TB>>>(ei);
    k_dinv_xs<<<gN, TB>>>(x);

    // layer 0: agg(x) -> @W_in+b_in,relu -> @W_h[0] prescaled -> m0
    k_aggx_gemm<<<gW4, TB>>>(W_in, b_in, W_h + 0 * HID * HID);

    // h2 = relu(agg(m0)+b_h[0]) -> @W_h[1] -> m1
    k_agg_gemm<<<gW4, TB>>>(m0, m1, b_h + 0 * HID, W_h + 1 * HID * HID);
    // h3 = relu(agg(m1)+b_h[1]) -> @W_h[2] -> m0
    k_agg_gemm<<<gW4, TB>>>(m1, m0, b_h + 1 * HID, W_h + 2 * HID * HID);
    // h4 = relu(agg(m0)+b_h[2]) -> z = di*(h4 . W_out)
    k_agg_last<<<gW, TB>>>(m0, b_h + 2 * HID, W_out);

    // out = di*(sum z + z_self) + b_out
    k_agg_scalar<<<gN, TB>>>(out, b_out);
}

// round 15
// speedup vs baseline: 1.7998x; 1.0027x over previous
#include <cuda_runtime.h>
#include <cuda_fp16.h>
#include <cuda_bf16.h>
#include <mma.h>
using namespace nvcuda;

#define NN 50000
#define NNP 50048  // padded to 128-row multiple (391*128)
#define NE 800000
#define HID 64
#define MAXD 128   // per-node bucket capacity (Poisson(16) tail @128 ~ 0)
#define NPW 4      // nodes per warp in gather kernels

// ---------------- scratch (device globals; no allocation allowed) -------------
__device__ float   g_xs[NN * 4];        // dinv[n] * x[n]
__device__ __half  g_h[NNP * HID];      // post-relu hidden state (fp16)
__device__ __half  g_m[NNP * HID];      // GEMM output, pre-scaled by dinv (fp16)
__device__ float   g_z[NN];             // pre-scaled final scalar
__device__ float   g_dinv[NNP];         // tail stays 0 (never written)
__device__ int     g_cnt[NN];
__device__ int     g_col[NN * MAXD];    // bucketed CSR (row n at n*MAXD)

// ---------------- CSR build (bucketed: count IS scatter) -----------------------
__global__ void k_zero_cnt() {
    int i = blockIdx.x * blockDim.x + threadIdx.x;
    if (i < NN) g_cnt[i] = 0;
}

__global__ void k_scatter_count(const int* __restrict__ ei) {
    int e = blockIdx.x * blockDim.x + threadIdx.x;
    if (e < NE) {
        int s = ei[e];
        int d = ei[NE + e];
        int pos = atomicAdd(&g_cnt[d], 1);
        if (pos < MAXD) g_col[d * MAXD + pos] = s;
    }
}

__global__ void k_dinv_xs(const float* __restrict__ x) {
    int i = blockIdx.x * blockDim.x + threadIdx.x;
    if (i < NN) {
        float di = rsqrtf((float)(g_cnt[i] + 1));  // +1 self loop
        g_dinv[i] = di;
        float4 v = ((const float4*)x)[i];
        v.x *= di; v.y *= di; v.z *= di; v.w *= di;
        ((float4*)g_xs)[i] = v;
    }
}

// ---- per-node fp16 gather with 8-deep MLP -------------------------------------
__device__ __forceinline__ void gather16(const __half2* __restrict__ A2, int n, int lane,
                                         float& axo, float& ayo) {
    float ax = 0.f, ay = 0.f;
    int base = n * MAXD;
    int len = min(g_cnt[n], MAXD);
    int j = 0;
    for (; j + 8 <= len; j += 8) {
        int4 c0 = *(const int4*)&g_col[base + j];
        int4 c1 = *(const int4*)&g_col[base + j + 4];
        float2 f0 = __half22float2(__ldg(&A2[c0.x * 32 + lane]));
        float2 f1 = __half22float2(__ldg(&A2[c0.y * 32 + lane]));
        float2 f2 = __half22float2(__ldg(&A2[c0.z * 32 + lane]));
        float2 f3 = __half22float2(__ldg(&A2[c0.w * 32 + lane]));
        float2 f4 = __half22float2(__ldg(&A2[c1.x * 32 + lane]));
        float2 f5 = __half22float2(__ldg(&A2[c1.y * 32 + lane]));
        float2 f6 = __half22float2(__ldg(&A2[c1.z * 32 + lane]));
        float2 f7 = __half22float2(__ldg(&A2[c1.w * 32 + lane]));
        ax += (f0.x + f1.x) + (f2.x + f3.x) + (f4.x + f5.x) + (f6.x + f7.x);
        ay += (f0.y + f1.y) + (f2.y + f3.y) + (f4.y + f5.y) + (f6.y + f7.y);
    }
    for (; j + 4 <= len; j += 4) {
        int4 c = *(const int4*)&g_col[base + j];
        float2 f0 = __half22float2(__ldg(&A2[c.x * 32 + lane]));
        float2 f1 = __half22float2(__ldg(&A2[c.y * 32 + lane]));
        float2 f2 = __half22float2(__ldg(&A2[c.z * 32 + lane]));
        float2 f3 = __half22float2(__ldg(&A2[c.w * 32 + lane]));
        ax += (f0.x + f1.x) + (f2.x + f3.x);
        ay += (f0.y + f1.y) + (f2.y + f3.y);
    }
    for (; j < len; j++) {
        float2 f = __half22float2(__ldg(&A2[g_col[base + j] * 32 + lane]));
        ax += f.x;
        ay += f.y;
    }
    float2 sv = __half22float2(A2[n * 32 + lane]);
    axo = ax + sv.x;
    ayo = ay + sv.y;
}

// ------- layer 0: agg(xs) -> h0 = relu(y@W_in + b) -> g_h (fp16) ---------------
__global__ void k_aggx(const float* __restrict__ W, const float* __restrict__ bias) {
    __shared__ float2 Ws2[4 * 32];
    __shared__ float2 Bs2[32];
    if (threadIdx.x < 128) {
        int k = threadIdx.x >> 5, l = threadIdx.x & 31;
        Ws2[k * 32 + l] = make_float2(W[k * HID + 2 * l], W[k * HID + 2 * l + 1]);
    }
    if (threadIdx.x < 32)
        Bs2[threadIdx.x] = make_float2(bias[2 * threadIdx.x], bias[2 * threadIdx.x + 1]);
    __syncthreads();

    int warp = (blockIdx.x * blockDim.x + threadIdx.x) >> 5;
    int lane = threadIdx.x & 31;
    int n0 = warp * NPW;
    if (n0 >= NN) return;
    const float4* xs4 = (const float4*)g_xs;

    #pragma unroll
    for (int i = 0; i < NPW; i++) {
        int n = n0 + i;
        float4 acc = make_float4(0.f, 0.f, 0.f, 0.f);
        int base = n * MAXD;
        int len = min(g_cnt[n], MAXD);
        for (int j = lane; j < len; j += 32) {
            float4 v = __ldg(&xs4[g_col[base + j]]);
            acc.x += v.x; acc.y += v.y; acc.z += v.z; acc.w += v.w;
        }
        #pragma unroll
        for (int o = 16; o; o >>= 1) {
            acc.x += __shfl_xor_sync(0xffffffffu, acc.x, o);
            acc.y += __shfl_xor_sync(0xffffffffu, acc.y, o);
            acc.z += __shfl_xor_sync(0xffffffffu, acc.z, o);
            acc.w += __shfl_xor_sync(0xffffffffu, acc.w, o);
        }
        float di = g_dinv[n];
        float4 sv = xs4[n];
        float y0 = di * (acc.x + sv.x);
        float y1 = di * (acc.y + sv.y);
        float y2 = di * (acc.z + sv.z);
        float y3 = di * (acc.w + sv.w);
        float2 b2 = Bs2[lane];
        float a0 = b2.x, a1 = b2.y;
        float2 w0 = Ws2[0 * 32 + lane], w1 = Ws2[1 * 32 + lane];
        float2 w2 = Ws2[2 * 32 + lane], w3 = Ws2[3 * 32 + lane];
        a0 = fmaf(y0, w0.x, a0); a1 = fmaf(y0, w0.y, a1);
        a0 = fmaf(y1, w1.x, a0); a1 = fmaf(y1, w1.y, a1);
        a0 = fmaf(y2, w2.x, a0); a1 = fmaf(y2, w2.y, a1);
        a0 = fmaf(y3, w3.x, a0); a1 = fmaf(y3, w3.y, a1);
        a0 = fmaxf(a0, 0.f);
        a1 = fmaxf(a1, 0.f);
        ((__half2*)g_h)[n * 32 + lane] = __floats2half2_rn(a0, a1);
    }
}

// ---- tensor-core GEMM: M = dinv .* (H @ W),  H[NNP,64] fp16, W fp32->fp16 -----
// block = 256 threads (8 warps), 128 rows per block, warp does 16 rows x 64 cols
__global__ void k_wmma(const __half* __restrict__ H, __half* __restrict__ M,
                       const float* __restrict__ W) {
    __shared__ __half Ws[HID * HID];          // 8 KB, row-major [k][n]
    __shared__ float  Os[8][16 * HID];        // 32 KB, per-warp output staging
    for (int i = threadIdx.x; i < HID * HID; i += blockDim.x)
        Ws[i] = __float2half(W[i]);
    __syncthreads();

    int w = threadIdx.x >> 5;
    int lane = threadIdx.x & 31;
    int row0 = blockIdx.x * 128 + w * 16;

    wmma::fragment<wmma::matrix_a, 16, 16, 16, __half, wmma::row_major> a[4];
    #pragma unroll
    for (int k = 0; k < 4; k++)
        wmma::load_matrix_sync(a[k], H + row0 * HID + k * 16, HID);

    #pragma unroll
    for (int nt = 0; nt < 4; nt++) {
        wmma::fragment<wmma::accumulator, 16, 16, 16, float> acc;
        wmma::fill_fragment(acc, 0.f);
        #pragma unroll
        for (int k = 0; k < 4; k++) {
            wmma::fragment<wmma::matrix_b, 16, 16, 16, __half, wmma::row_major> b;
            wmma::load_matrix_sync(b, Ws + (k * 16) * HID + nt * 16, HID);
            wmma::mma_sync(acc, a[k], b, acc);
        }
        wmma::store_matrix_sync(&Os[w][nt * 16], acc, HID, wmma::mem_row_major);
    }
    __syncwarp();

    // epilogue: scale by dinv[row], pack to half2
    for (int idx = lane; idx < 16 * 32; idx += 32) {
        int r = idx >> 5, c = idx & 31;
        float di = g_dinv[row0 + r];
        float f0 = Os[w][r * HID + 2 * c];
        float f1 = Os[w][r * HID + 2 * c + 1];
        ((__half2*)M)[(row0 + r) * 32 + c] = __floats2half2_rn(f0 * di, f1 * di);
    }
}

// ---- hidden gather: h' = relu(di*(agg m) + b) -> g_h (fp16) -------------------
__global__ void k_agg(const __half* __restrict__ srcbuf, __half* __restrict__ dstbuf,
                      const float* __restrict__ bias) {
    __shared__ float2 Bs2[32];
    if (threadIdx.x < 32)
        Bs2[threadIdx.x] = make_float2(bias[2 * threadIdx.x], bias[2 * threadIdx.x + 1]);
    __syncthreads();

    int warp = (blockIdx.x * blockDim.x + threadIdx.x) >> 5;
    int lane = threadIdx.x & 31;
    int n0 = warp * NPW;
    if (n0 >= NN) return;
    const __half2* A2 = (const __half2*)srcbuf;

    #pragma unroll
    for (int i = 0; i < NPW; i++) {
        int n = n0 + i;
        float ax, ay;
        gather16(A2, n, lane, ax, ay);
        float di = g_dinv[n];
        float2 b2 = Bs2[lane];
        ax = fmaxf(fmaf(di, ax, b2.x), 0.f);
        ay = fmaxf(fmaf(di, ay, b2.y), 0.f);
        ((__half2*)dstbuf)[n * 32 + lane] = __floats2half2_rn(ax, ay);
    }
}

// ---- last hidden layer: gather -> h=relu(di*agg+b) -> z = di*(h.Wout) ---------
__global__ void k_agg_last(const __half* __restrict__ srcbuf,
                           const float* __restrict__ bias, const float* __restrict__ Wout) {
    int warp = (blockIdx.x * blockDim.x + threadIdx.x) >> 5;
    int lane = threadIdx.x & 31;
    if (warp >= NN) return;
    int n = warp;
    const __half2* A2 = (const __half2*)srcbuf;
    float ax, ay;
    gather16(A2, n, lane, ax, ay);
    float di = g_dinv[n];
    float2 b2 = ((const float2*)bias)[lane];
    ax = fmaxf(fmaf(di, ax, b2.x), 0.f);
    ay = fmaxf(fmaf(di, ay, b2.y), 0.f);
    float2 w2 = ((const float2*)Wout)[lane];
    float s = ax * w2.x + ay * w2.y;
    #pragma unroll
    for (int o = 16; o; o >>= 1) s += __shfl_xor_sync(0xffffffffu, s, o);
    if (lane == 0) g_z[n] = di * s;
}

// ---- final scalar aggregation ------------------------------------------------
__global__ void k_agg_scalar(float* __restrict__ out, const float* __restrict__ b_out) {
    int n = blockIdx.x * blockDim.x + threadIdx.x;
    if (n < NN) {
        float acc = 0.f;
        int base = n * MAXD;
        int len = min(g_cnt[n], MAXD);
        int j = 0;
        for (; j + 8 <= len; j += 8) {
            int4 c0 = *(const int4*)&g_col[base + j];
            int4 c1 = *(const int4*)&g_col[base + j + 4];
            float z0 = __ldg(&g_z[c0.x]), z1 = __ldg(&g_z[c0.y]);
            float z2 = __ldg(&g_z[c0.z]), z3 = __ldg(&g_z[c0.w]);
            float z4 = __ldg(&g_z[c1.x]), z5 = __ldg(&g_z[c1.y]);
            float z6 = __ldg(&g_z[c1.z]), z7 = __ldg(&g_z[c1.w]);
            acc += (z0 + z1) + (z2 + z3) + (z4 + z5) + (z6 + z7);
        }
        for (; j + 4 <= len; j += 4) {
            int4 c = *(const int4*)&g_col[base + j];
            acc += __ldg(&g_z[c.x]) + __ldg(&g_z[c.y]) + __ldg(&g_z[c.z]) + __ldg(&g_z[c.w]);
        }
        for (; j < len; j++) acc += __ldg(&g_z[g_col[base + j]]);
        acc += g_z[n];
        out[n] = fmaf(g_dinv[n], acc, b_out[0]);
    }
}

// ---------------- launch ------------------------------------------------------
extern "C" void kernel_launch(void* const* d_in, const int* in_sizes, int n_in,
                              void* d_out, int out_size) {
    const float* x     = (const float*)d_in[0];
    const int*   ei    = (const int*)d_in[1];
    const float* W_in  = (const float*)d_in[2];
    const float* b_in  = (const float*)d_in[3];
    const float* W_h   = (const float*)d_in[4];
    const float* b_h   = (const float*)d_in[5];
    const float* W_out = (const float*)d_in[6];
    const float* b_out = (const float*)d_in[7];
    float*       out   = (float*)d_out;

    const int TB = 256;
    const int gN  = (NN + TB - 1) / TB;
    const int gE  = (NE + TB - 1) / TB;
    const int gW  = (NN * 32 + TB - 1) / TB;            // warp per node
    const int nWarp4 = (NN + NPW - 1) / NPW;            // 12500
    const int gW4 = (nWarp4 * 32 + TB - 1) / TB;        // gather kernels
    const int gMM = NNP / 128;                          // 391 wmma blocks

    __half* h; cudaGetSymbolAddress((void**)&h, g_h);
    __half* m; cudaGetSymbolAddress((void**)&m, g_m);

    // CSR build
    k_zero_cnt<<<gN, TB>>>();
    k_scatter_count<<<gE, TB>>>(ei);
    k_dinv_xs<<<gN, TB>>>(x);

    // layer 0: agg(x) -> h0 = relu(y@W_in+b) -> g_h
    k_aggx<<<gW4, TB>>>(W_in, b_in);

    // hidden layers 1-2: tensor-core GEMM then gather
    for (int l = 0; l < 2; l++) {
        k_wmma<<<gMM, TB>>>(h, m, W_h + l * HID * HID);
        k_agg<<<gW4, TB>>>(m, h, b_h + l * HID);
    }
    // layer 3: GEMM then gather fused with output GEMV
    k_wmma<<<gMM, TB>>>(h, m, W_h + 2 * HID * HID);
    k_agg_last<<<gW, TB>>>(m, b_h + 2 * HID, W_out);

    // out = di*(sum z + z_self) + b_out
    k_agg_scalar<<<gN, TB>>>(out, b_out);
}